// round 1
// baseline (speedup 1.0000x reference)
#include <cuda_runtime.h>
#include <math.h>

#define DIM     256
#define HEADS   8
#define HDIM    32
#define GW      64
#define HW      56
#define NPIX    3136            // 56*56
#define BATCH   16
#define NTOK    (BATCH * NPIX)  // 50176
#define HIDDEN  1024
#define LN_EPS  1e-6f
#define BN_EPS  1e-3f
#define L2_EPS  1e-12f
#define SCALE_Q 0.17677669529663689f  // 32^-0.5

// ---------------- scratch (static device globals; no cudaMalloc allowed) ----
__device__ float d_dwconv [NTOK * DIM];
__device__ float d_norm1  [NTOK * DIM];
__device__ float d_qkv    [NTOK * 3 * DIM];
__device__ float d_attn   [BATCH * HEADS * HDIM * HDIM];
__device__ float d_attnout[NTOK * DIM];
__device__ float d_merged [NTOK * DIM];
__device__ float d_h1     [NTOK * HIDDEN];

// ---------------- kernel 1: dwconv3x3 (192ch) + group cumsum + LayerNorm ----
__global__ void __launch_bounds__(256) dwln_kernel(
    const float* __restrict__ x, const float* __restrict__ dwk,
    const float* __restrict__ dwb, const float* __restrict__ g,
    const float* __restrict__ be)
{
    int pix = blockIdx.x;          // 0..NTOK-1
    int c   = threadIdx.x;         // 0..255
    int b   = pix / NPIX;
    int p   = pix % NPIX;
    int hh  = p / HW, ww = p % HW;

    __shared__ float sK[192];
    __shared__ float red[256];

    float v;
    if (c < GW) {
        v = x[pix * DIM + c];
    } else {
        int cc = c - GW;                 // 0..191
        float acc = dwb[cc];
        #pragma unroll
        for (int ky = 0; ky < 3; ky++) {
            int hy = hh + ky - 1;
            if ((unsigned)hy < (unsigned)HW) {
                #pragma unroll
                for (int kx = 0; kx < 3; kx++) {
                    int wx = ww + kx - 1;
                    if ((unsigned)wx < (unsigned)HW) {
                        acc += x[((b * HW + hy) * HW + wx) * DIM + c] *
                               dwk[(ky * 3 + kx) * 192 + cc];
                    }
                }
            }
        }
        sK[cc] = acc;
    }
    __syncthreads();
    if (c >= GW) {
        int cc = c - GW;
        int j  = cc & 63;
        int gi = cc >> 6;          // group 0,1,2
        float s = sK[j];
        if (gi >= 1) s += sK[64 + j];
        if (gi >= 2) s += sK[128 + j];
        v = s;
    }
    // LayerNorm over 256 channels
    red[c] = v; __syncthreads();
    #pragma unroll
    for (int s = 128; s > 0; s >>= 1) { if (c < s) red[c] += red[c + s]; __syncthreads(); }
    float mean = red[0] * (1.0f / 256.0f);
    __syncthreads();
    float dv = v - mean;
    red[c] = dv * dv; __syncthreads();
    #pragma unroll
    for (int s = 128; s > 0; s >>= 1) { if (c < s) red[c] += red[c + s]; __syncthreads(); }
    float var = red[0] * (1.0f / 256.0f);

    float rstd = rsqrtf(var + LN_EPS);
    d_dwconv[pix * DIM + c] = v;
    d_norm1 [pix * DIM + c] = dv * rstd * g[c] + be[c];
}

// ---------------- kernel 2: l2norm q/k in-place (one warp per token-head) ---
__global__ void __launch_bounds__(256) l2norm_kernel()
{
    int gwid = blockIdx.x * 8 + (threadIdx.x >> 5);
    if (gwid >= NTOK * HEADS) return;
    int lane = threadIdx.x & 31;
    int tok  = gwid >> 3;
    int h    = gwid & 7;
    int base = tok * 768 + h * HDIM + lane;

    float q = d_qkv[base];
    float ss = q * q;
    #pragma unroll
    for (int o = 16; o; o >>= 1) ss += __shfl_xor_sync(0xffffffffu, ss, o);
    d_qkv[base] = q * rsqrtf(fmaxf(ss, L2_EPS)) * SCALE_Q;

    float k = d_qkv[base + 256];
    ss = k * k;
    #pragma unroll
    for (int o = 16; o; o >>= 1) ss += __shfl_xor_sync(0xffffffffu, ss, o);
    d_qkv[base + 256] = k * rsqrtf(fmaxf(ss, L2_EPS));
}

// ---------------- kernel 3: attn[d][e] = softmax_e( sum_n q[n,d] k[n,e] ) ---
__global__ void __launch_bounds__(1024) attn_kernel()
{
    int b = blockIdx.x >> 3;
    int h = blockIdx.x & 7;
    int d = threadIdx.y, e = threadIdx.x;

    __shared__ float qs[32][32];
    __shared__ float ks[32][32];

    float acc = 0.f;
    long base = (long)(b * NPIX) * 768 + h * HDIM;
    for (int t = 0; t < NPIX / 32; t++) {
        long row = base + (long)(t * 32 + d) * 768;
        qs[d][e] = d_qkv[row + e];
        ks[d][e] = d_qkv[row + 256 + e];
        __syncthreads();
        #pragma unroll
        for (int i = 0; i < 32; i++)
            acc += qs[i][d] * ks[i][e];
        __syncthreads();
    }
    // softmax over e (one warp == one row d)
    float m = acc;
    #pragma unroll
    for (int o = 16; o; o >>= 1) m = fmaxf(m, __shfl_xor_sync(0xffffffffu, m, o));
    float ex = expf(acc - m);
    float s = ex;
    #pragma unroll
    for (int o = 16; o; o >>= 1) s += __shfl_xor_sync(0xffffffffu, s, o);
    d_attn[((b * HEADS + h) * HDIM + d) * HDIM + e] = ex / s;
}

// ---------------- kernel 4: out[n, h*32+e] = sum_d v[n,d] attn[h,d,e] -------
__global__ void __launch_bounds__(256) av_kernel()
{
    int b     = blockIdx.y;
    int chunk = blockIdx.x;     // 0..97
    int tid   = threadIdx.x;    // 0..255

    __shared__ float sA[HEADS * HDIM * HDIM];  // 8192 floats
    __shared__ float sV[256];

    for (int i = tid; i < HEADS * HDIM * HDIM; i += 256)
        sA[i] = d_attn[b * HEADS * HDIM * HDIM + i];
    __syncthreads();

    int h = tid >> 5, e = tid & 31;
    const float* Ah = &sA[h * HDIM * HDIM];
    for (int t = 0; t < 32; t++) {
        int tok = b * NPIX + chunk * 32 + t;
        sV[tid] = d_qkv[(long)tok * 768 + 512 + tid];
        __syncthreads();
        float acc = 0.f;
        #pragma unroll
        for (int dd = 0; dd < 32; dd++)
            acc += sV[h * 32 + dd] * Ah[dd * 32 + e];
        d_attnout[(long)tok * DIM + tid] = acc;
        __syncthreads();
    }
}

// ---------------- tiled SGEMM with fused epilogues ---------------------------
// MODE 0: plain C = A*B                          (qkv)
// MODE 1: C = BN( A*B + bias + add1 )            (proj + dwconv + batchnorm)
// MODE 2: C = gelu( A*B + bias )                 (fc1)
// MODE 3: C = A*B + bias + add1                  (fc2 + x residual)
template<int MODE>
__global__ void __launch_bounds__(256) sgemm_kernel(
    const float* __restrict__ A, const float* __restrict__ Bm,
    float* __restrict__ C, int M, int N, int K,
    const float* __restrict__ bias, const float* __restrict__ add1,
    const float* __restrict__ bn_g, const float* __restrict__ bn_b,
    const float* __restrict__ bn_m, const float* __restrict__ bn_v)
{
    const int BM = 64, BN = 64, BK = 16;
    __shared__ float As[BK][BM];
    __shared__ float Bs[BK][BN];

    int m0 = blockIdx.y * BM;
    int n0 = blockIdx.x * BN;
    int tid = threadIdx.x;
    int tx = tid & 15, ty = tid >> 4;

    int arow  = tid >> 2;
    int acol4 = (tid & 3) * 4;
    int brow  = tid >> 4;
    int bcol4 = (tid & 15) * 4;

    float acc[4][4] = {};

    for (int k0 = 0; k0 < K; k0 += BK) {
        float4 av = *reinterpret_cast<const float4*>(&A[(long)(m0 + arow) * K + k0 + acol4]);
        As[acol4 + 0][arow] = av.x;
        As[acol4 + 1][arow] = av.y;
        As[acol4 + 2][arow] = av.z;
        As[acol4 + 3][arow] = av.w;
        *reinterpret_cast<float4*>(&Bs[brow][bcol4]) =
            *reinterpret_cast<const float4*>(&Bm[(long)(k0 + brow) * N + n0 + bcol4]);
        __syncthreads();
        #pragma unroll
        for (int kk = 0; kk < BK; kk++) {
            float a[4], bv[4];
            #pragma unroll
            for (int i = 0; i < 4; i++) a[i]  = As[kk][ty * 4 + i];
            #pragma unroll
            for (int j = 0; j < 4; j++) bv[j] = Bs[kk][tx * 4 + j];
            #pragma unroll
            for (int i = 0; i < 4; i++)
                #pragma unroll
                for (int j = 0; j < 4; j++)
                    acc[i][j] += a[i] * bv[j];
        }
        __syncthreads();
    }

    #pragma unroll
    for (int i = 0; i < 4; i++) {
        int row = m0 + ty * 4 + i;
        #pragma unroll
        for (int j = 0; j < 4; j++) {
            int col = n0 + tx * 4 + j;
            float v = acc[i][j];
            if (MODE == 1) {
                v += bias[col] + add1[(long)row * N + col];
                v = (v - bn_m[col]) * rsqrtf(bn_v[col] + BN_EPS) * bn_g[col] + bn_b[col];
            } else if (MODE == 2) {
                v += bias[col];
                v = 0.5f * v * (1.0f + erff(v * 0.70710678118654752f));
            } else if (MODE == 3) {
                v += bias[col] + add1[(long)row * N + col];
            }
            C[(long)row * N + col] = v;
        }
    }
}

// ---------------- launch ------------------------------------------------------
extern "C" void kernel_launch(void* const* d_in, const int* in_sizes, int n_in,
                              void* d_out, int out_size)
{
    const float* x        = (const float*)d_in[0];
    const float* dw_kernel= (const float*)d_in[1];
    const float* dw_bias  = (const float*)d_in[2];
    const float* ln_gamma = (const float*)d_in[3];
    const float* ln_beta  = (const float*)d_in[4];
    const float* qkv_w    = (const float*)d_in[5];
    const float* proj_w   = (const float*)d_in[6];
    const float* proj_b   = (const float*)d_in[7];
    const float* bn_gamma = (const float*)d_in[8];
    const float* bn_beta  = (const float*)d_in[9];
    const float* bn_mean  = (const float*)d_in[10];
    const float* bn_var   = (const float*)d_in[11];
    const float* fc1_w    = (const float*)d_in[12];
    const float* fc1_b    = (const float*)d_in[13];
    const float* fc2_w    = (const float*)d_in[14];
    const float* fc2_b    = (const float*)d_in[15];
    float* out = (float*)d_out;

    float *p_dwconv, *p_norm1, *p_qkv, *p_attnout, *p_merged, *p_h1;
    cudaGetSymbolAddress((void**)&p_dwconv,  d_dwconv);
    cudaGetSymbolAddress((void**)&p_norm1,   d_norm1);
    cudaGetSymbolAddress((void**)&p_qkv,     d_qkv);
    cudaGetSymbolAddress((void**)&p_attnout, d_attnout);
    cudaGetSymbolAddress((void**)&p_merged,  d_merged);
    cudaGetSymbolAddress((void**)&p_h1,      d_h1);

    // 1) dwconv + cumsum + LN
    dwln_kernel<<<NTOK, 256>>>(x, dw_kernel, dw_bias, ln_gamma, ln_beta);

    // 2) qkv = norm1 @ qkv_w   [50176 x 768 x 256]
    sgemm_kernel<0><<<dim3(768 / 64, NTOK / 64), 256>>>(
        p_norm1, qkv_w, p_qkv, NTOK, 768, 256,
        nullptr, nullptr, nullptr, nullptr, nullptr, nullptr);

    // 3) l2-normalize q (and scale) and k in-place
    l2norm_kernel<<<NTOK * HEADS / 8, 256>>>();

    // 4) attn = softmax(q^T k) per (b,h)  [32x32 each]
    attn_kernel<<<BATCH * HEADS, dim3(32, 32)>>>();

    // 5) out = v @ attn
    av_kernel<<<dim3(NPIX / 32, BATCH), 256>>>();

    // 6) merged = BN(attnout @ proj_w + proj_b + dwconv)
    sgemm_kernel<1><<<dim3(256 / 64, NTOK / 64), 256>>>(
        p_attnout, proj_w, p_merged, NTOK, 256, 256,
        proj_b, p_dwconv, bn_gamma, bn_beta, bn_mean, bn_var);

    // 7) h1 = gelu(merged @ fc1_w + fc1_b)
    sgemm_kernel<2><<<dim3(1024 / 64, NTOK / 64), 256>>>(
        p_merged, fc1_w, p_h1, NTOK, 1024, 256,
        fc1_b, nullptr, nullptr, nullptr, nullptr, nullptr);

    // 8) out = h1 @ fc2_w + fc2_b + x
    sgemm_kernel<3><<<dim3(256 / 64, NTOK / 64), 256>>>(
        p_h1, fc2_w, out, NTOK, 256, 1024,
        fc2_b, x, nullptr, nullptr, nullptr, nullptr);
}